// round 1
// baseline (speedup 1.0000x reference)
#include <cuda_runtime.h>
#include <math_constants.h>

#define KS      7
#define STRIDE  2
#define PADW    3            // KS/2
#define TILE    32           // output tile (square)
#define IN_TILE (STRIDE*(TILE-1) + KS)   // 69
#define SROW    72           // padded smem row stride (floats)

#define H_IN  256
#define W_IN  256
#define H_OUT 128
#define W_OUT 128

__global__ __launch_bounds__(256, 4)
void parabolic_pool_kernel(const float* __restrict__ f,
                           const float* __restrict__ tptr,
                           float* __restrict__ out)
{
    const int plane = blockIdx.z;                 // b*C + c
    const int i0 = blockIdx.y * TILE;             // output tile origin (rows)
    const int j0 = blockIdx.x * TILE;             // output tile origin (cols)

    const float* __restrict__ fp = f   + (size_t)plane * (H_IN  * W_IN);
    float*       __restrict__ op = out + (size_t)plane * (H_OUT * W_OUT);

    // parabolic kernel is separable under max-plus: h[u,v] = hu[u] + hv[v]
    const float inv4t = 1.0f / (4.0f * (*tptr));
    float h1[KS];
#pragma unroll
    for (int u = 0; u < KS; ++u) {
        float z = (float)(u - PADW);
        h1[u] = -z * z * inv4t;
    }

    __shared__ float s[IN_TILE][SROW];   // raw input halo tile
    __shared__ float g[TILE][SROW];      // after vertical max-plus pass

    const int tid = threadIdx.x;
    const int r0 = i0 * STRIDE - PADW;   // global row of s[0][*]
    const int c0 = j0 * STRIDE - PADW;   // global col of s[*][0]

    // ---- load 69x69 halo tile (OOB = -inf, i.e. morphological pad) ----
    for (int idx = tid; idx < IN_TILE * IN_TILE; idx += 256) {
        int r = idx / IN_TILE;
        int c = idx - r * IN_TILE;
        int rg = r0 + r;
        int cg = c0 + c;
        float v = -CUDART_INF_F;
        if (rg >= 0 && rg < H_IN && cg >= 0 && cg < W_IN)
            v = fp[rg * W_IN + cg];
        s[r][c] = v;
    }
    __syncthreads();

    // ---- vertical pass: g[i][x] = max_u s[2i+u][x] + hu[u] ----
    for (int idx = tid; idx < TILE * IN_TILE; idx += 256) {
        int i = idx / IN_TILE;
        int x = idx - i * IN_TILE;
        float m = -CUDART_INF_F;
#pragma unroll
        for (int u = 0; u < KS; ++u)
            m = fmaxf(m, s[STRIDE * i + u][x] + h1[u]);
        g[i][x] = m;
    }
    __syncthreads();

    // ---- horizontal pass: out[i][j] = max_v g[i][2j+v] + hv[v] ----
    for (int idx = tid; idx < TILE * TILE; idx += 256) {
        int i = idx >> 5;          // /32
        int j = idx & 31;          // %32
        float m = -CUDART_INF_F;
#pragma unroll
        for (int v = 0; v < KS; ++v)
            m = fmaxf(m, g[i][STRIDE * j + v] + h1[v]);
        op[(i0 + i) * W_OUT + (j0 + j)] = m;
    }
}

extern "C" void kernel_launch(void* const* d_in, const int* in_sizes, int n_in,
                              void* d_out, int out_size)
{
    const float* f = (const float*)d_in[0];
    const float* t = (const float*)d_in[1];
    float* out = (float*)d_out;

    // f: (16,128,256,256) -> 2048 planes; out: (16,128,128,128)
    dim3 grid(W_OUT / TILE, H_OUT / TILE, 16 * 128);
    parabolic_pool_kernel<<<grid, 256>>>(f, t, out);
}

// round 2
// speedup vs baseline: 2.9939x; 2.9939x over previous
#include <cuda_runtime.h>
#include <math_constants.h>

#define H_IN   256
#define W_IN   256
#define H_OUT  128
#define W_OUT  128
#define SROW   264            // 4 -inf pad | 256 data | 4 -inf pad
#define NEG_INF (-CUDART_INF_F)

// Horizontal 7-tap max-plus for output column j from a padded smem row.
// Window global cols 2j-3..2j+3  ->  smem idx 2j+1..2j+7 (pad offset +4).
// Symmetric weights: h[o] = -o^2/(4t) -> pair-max then add.
__device__ __forceinline__ float horiz7(const float* __restrict__ row, int j,
                                        float h1, float h2, float h3)
{
    float  a  = row[2*j + 1];                         // o = -3
    float2 bc = *(const float2*)(row + 2*j + 2);      // o = -2, -1
    float2 cc = *(const float2*)(row + 2*j + 4);      // o =  0, +1
    float2 dd = *(const float2*)(row + 2*j + 6);      // o = +2, +3
    float m1 = fmaxf(bc.y, cc.y) + h1;
    float m2 = fmaxf(bc.x, dd.x) + h2;
    float m3 = fmaxf(a,    dd.y) + h3;
    return fmaxf(fmaxf(cc.x, m1), fmaxf(m2, m3));
}

__global__ __launch_bounds__(128, 12)
void parabolic_pool_kernel(const float* __restrict__ f,
                           const float* __restrict__ tptr,
                           float* __restrict__ out)
{
    __shared__ float s[4][SROW];

    const int plane = blockIdx.x >> 1;
    const int i0    = (blockIdx.x & 1) * 64;      // output-row strip origin (0 or 64)
    const int j     = threadIdx.x;                // output column 0..127

    const float* __restrict__ fp = f + (size_t)plane * (H_IN * W_IN);
    float* __restrict__ op = out + (size_t)plane * (H_OUT * W_OUT) + (size_t)i0 * W_OUT;

    const float inv4t = 0.25f / tptr[0];
    const float h1 = -1.0f * inv4t;
    const float h2 = -4.0f * inv4t;
    const float h3 = -9.0f * inv4t;

    // one-time -inf pads (horizontal OOB), visible after first barrier
    if (j < 4) {
#pragma unroll
        for (int b = 0; b < 4; ++b) {
            s[b][j]       = NEG_INF;
            s[b][260 + j] = NEG_INF;
        }
    }

    // Register ring: g-row for input row R lives in ring[R & 7] (2*i0 % 8 == 0).
    float ring[8];

    // ---- prologue: input rows 2*i0-3 .. 2*i0+3 ----
#pragma unroll
    for (int k = 0; k < 7; ++k) {
        const int r = 2 * i0 - 3 + k;             // may be negative only for i0=0
        if (r >= 0) {
            float2 v = *(const float2*)(fp + r * W_IN + 2 * j);
            *(float2*)(&s[(k + 1) & 3][4 + 2 * j]) = v;   // (r&3) == (k+1)&3
        }
        __syncthreads();
        ring[(k + 5) & 7] = (r >= 0) ? horiz7(s[(k + 1) & 3], j, h1, h2, h3)
                                     : NEG_INF;
    }

    // initial prefetch: rows 2*i0+4, 2*i0+5 (always in-bounds, max 133)
    float2 va = *(const float2*)(fp + (2 * i0 + 4) * W_IN + 2 * j);
    float2 vb = *(const float2*)(fp + (2 * i0 + 5) * W_IN + 2 * j);

    // ---- body: 64 output rows, unrolled x4 so ring/slot indices are static ----
    for (int ib = 0; ib < 16; ++ib) {
#pragma unroll
        for (int ip = 0; ip < 4; ++ip) {
            const int i = ib * 4 + ip;            // local output row

            // vertical max-plus from ring: window rows 2I-3..2I+3, center slot 2*ip
            float ctr = ring[(2 * ip) & 7];
            float p1 = fmaxf(ring[(2 * ip + 7) & 7], ring[(2 * ip + 1) & 7]) + h1;
            float p2 = fmaxf(ring[(2 * ip + 6) & 7], ring[(2 * ip + 2) & 7]) + h2;
            float p3 = fmaxf(ring[(2 * ip + 5) & 7], ring[(2 * ip + 3) & 7]) + h3;
            op[i * W_OUT + j] = fmaxf(fmaxf(ctr, p1), fmaxf(p2, p3));

            // stage prefetched rows 2I+4, 2I+5
            const int sa = (2 * ip + 4) & 3;
            const int sb = (2 * ip + 5) & 3;
            *(float2*)(&s[sa][4 + 2 * j]) = va;
            *(float2*)(&s[sb][4 + 2 * j]) = vb;
            __syncthreads();

            // prefetch rows 2I+6, 2I+7 for next iteration (guard bottom edge)
            const int rn = 2 * (i0 + i) + 6;
            va = (rn     < H_IN) ? *(const float2*)(fp + rn * W_IN + 2 * j)
                                 : make_float2(NEG_INF, NEG_INF);
            vb = (rn + 1 < H_IN) ? *(const float2*)(fp + (rn + 1) * W_IN + 2 * j)
                                 : make_float2(NEG_INF, NEG_INF);

            // horizontal pass on the two just-staged rows -> ring
            ring[(2 * ip + 4) & 7] = horiz7(s[sa], j, h1, h2, h3);
            ring[(2 * ip + 5) & 7] = horiz7(s[sb], j, h1, h2, h3);
        }
    }
}

extern "C" void kernel_launch(void* const* d_in, const int* in_sizes, int n_in,
                              void* d_out, int out_size)
{
    const float* f = (const float*)d_in[0];
    const float* t = (const float*)d_in[1];
    float* out = (float*)d_out;

    // 2048 planes x 2 half-strips
    parabolic_pool_kernel<<<2048 * 2, 128>>>(f, t, out);
}

// round 3
// speedup vs baseline: 3.0895x; 1.0319x over previous
#include <cuda_runtime.h>
#include <math_constants.h>

#define H_IN   256
#define W_IN   256
#define H_OUT  128
#define W_OUT  128
#define NEG_INF (-CUDART_INF_F)

struct Row {
    float4 v;    // own input cols cb..cb+3
    float4 eL;   // lane 0 only: cols cb-4..cb-1 (need .y .z .w)
    float2 eR;   // lane 31 only: cols cb+4, cb+5
};

// Load one input row's worth of data for this lane (r may be out of range -> -inf).
__device__ __forceinline__ Row ldrow(const float* __restrict__ fp, int r, int cb,
                                     bool ldL, bool ldR)
{
    Row x;
    x.v  = make_float4(NEG_INF, NEG_INF, NEG_INF, NEG_INF);
    x.eL = make_float4(NEG_INF, NEG_INF, NEG_INF, NEG_INF);
    x.eR = make_float2(NEG_INF, NEG_INF);
    if (r >= 0 && r < H_IN) {
        const float* rp = fp + r * W_IN;
        x.v = *(const float4*)(rp + cb);
        if (ldL) x.eL = *(const float4*)(rp + cb - 4);
        if (ldR) x.eR = *(const float2*)(rp + cb + 4);
    }
    return x;
}

// Horizontal 7-tap max-plus for the lane's two output columns.
// Out A center = v.x (col cb), out B center = v.z (col cb+2).
__device__ __forceinline__ float2 hmax(const Row& x, int lane,
                                       float h1, float h2, float h3)
{
    float m3 = __shfl_up_sync(0xffffffffu, x.v.y, 1);   // col cb-3
    float m2 = __shfl_up_sync(0xffffffffu, x.v.z, 1);   // col cb-2
    float m1 = __shfl_up_sync(0xffffffffu, x.v.w, 1);   // col cb-1
    float p4 = __shfl_down_sync(0xffffffffu, x.v.x, 1); // col cb+4
    float p5 = __shfl_down_sync(0xffffffffu, x.v.y, 1); // col cb+5
    if (lane == 0)  { m3 = x.eL.y; m2 = x.eL.z; m1 = x.eL.w; }
    if (lane == 31) { p4 = x.eR.x; p5 = x.eR.y; }

    float gA = fmaxf(fmaxf(x.v.x,               fmaxf(m2,    x.v.z) + h2),
                     fmaxf(fmaxf(m1,    x.v.y) + h1, fmaxf(m3, x.v.w) + h3));
    float gB = fmaxf(fmaxf(x.v.z,               fmaxf(x.v.x, p4)    + h2),
                     fmaxf(fmaxf(x.v.y, x.v.w) + h1, fmaxf(m1, p5)    + h3));
    return make_float2(gA, gB);
}

__device__ __forceinline__ float2 vmax(const float2* ring, int s0,
                                       float h1, float h2, float h3)
{
    float2 c  = ring[s0 & 7];
    float2 a1 = ring[(s0 + 7) & 7], b1 = ring[(s0 + 1) & 7];
    float2 a2 = ring[(s0 + 6) & 7], b2 = ring[(s0 + 2) & 7];
    float2 a3 = ring[(s0 + 5) & 7], b3 = ring[(s0 + 3) & 7];
    float2 o;
    o.x = fmaxf(fmaxf(c.x, fmaxf(a1.x, b1.x) + h1),
                fmaxf(fmaxf(a2.x, b2.x) + h2, fmaxf(a3.x, b3.x) + h3));
    o.y = fmaxf(fmaxf(c.y, fmaxf(a1.y, b1.y) + h1),
                fmaxf(fmaxf(a2.y, b2.y) + h2, fmaxf(a3.y, b3.y) + h3));
    return o;
}

__global__ __launch_bounds__(128)
void parabolic_pool_kernel(const float* __restrict__ f,
                           const float* __restrict__ tptr,
                           float* __restrict__ out)
{
    // global warp id -> (plane, col-half, row-strip); warps in a block share a plane
    const int gw    = blockIdx.x * 4 + (threadIdx.x >> 5);
    const int lane  = threadIdx.x & 31;
    const int plane = gw >> 2;
    const int c0    = ((gw >> 1) & 1) * 128;   // input col base of this warp
    const int i0    = (gw & 1) * 64;           // output row strip origin
    const int cb    = c0 + 4 * lane;           // this lane's input col base

    // edge-patch loads: left halo exists only for the right half; right halo
    // (cols 128,129) only for the left half
    const bool ldL = (lane == 0)  && (c0 != 0);
    const bool ldR = (lane == 31) && (c0 == 0);

    const float* __restrict__ fp = f + (size_t)plane * (H_IN * W_IN);
    float* __restrict__ op = out + (size_t)plane * (H_OUT * W_OUT)
                                 + (size_t)i0 * W_OUT + c0 / 2 + 2 * lane;

    const float inv4t = 0.25f / tptr[0];
    const float h1 = -1.0f * inv4t;
    const float h2 = -4.0f * inv4t;
    const float h3 = -9.0f * inv4t;

    // register ring: horizontal result of input row R lives in ring[R & 7]
    float2 ring[8];

    // ---- prologue: input rows 2*i0-3 .. 2*i0+3 ----
#pragma unroll
    for (int k = 0; k < 7; ++k) {
        Row x = ldrow(fp, 2 * i0 - 3 + k, cb, ldL, ldR);
        ring[(k + 5) & 7] = hmax(x, lane, h1, h2, h3);
    }

    // initial prefetch: rows 2*i0+4, 2*i0+5 (always in range)
    Row pva = ldrow(fp, 2 * i0 + 4, cb, ldL, ldR);
    Row pvb = ldrow(fp, 2 * i0 + 5, cb, ldL, ldR);

    // ---- body: 64 output rows, unrolled x4 for static ring indices ----
    for (int ib = 0; ib < 16; ++ib) {
#pragma unroll
        for (int ip = 0; ip < 4; ++ip) {
            const int i = ib * 4 + ip;                 // local output row

            // vertical max-plus and store (center input row 2*(i0+i) -> slot 2*ip)
            float2 o = vmax(ring, 2 * ip, h1, h2, h3);
            *(float2*)(op + i * W_OUT) = o;

            // rotate prefetched rows into the pipeline
            Row na = pva, nb = pvb;
            const int rn = 2 * (i0 + i) + 6;
            pva = ldrow(fp, rn,     cb, ldL, ldR);     // issues LDG early
            pvb = ldrow(fp, rn + 1, cb, ldL, ldR);

            ring[(2 * ip + 4) & 7] = hmax(na, lane, h1, h2, h3);
            ring[(2 * ip + 5) & 7] = hmax(nb, lane, h1, h2, h3);
        }
    }
}

extern "C" void kernel_launch(void* const* d_in, const int* in_sizes, int n_in,
                              void* d_out, int out_size)
{
    const float* f = (const float*)d_in[0];
    const float* t = (const float*)d_in[1];
    float* out = (float*)d_out;

    // 2048 planes x 2 col-halves x 2 row-strips = 8192 warps = 2048 blocks x 128 thr
    parabolic_pool_kernel<<<2048, 128>>>(f, t, out);
}